// round 2
// baseline (speedup 1.0000x reference)
#include <cuda_runtime.h>

// Problem dims (fixed by the dataset problem)
#define BB 4
#define TT 4096
#define EE 1024
#define HH 64
#define BT (BB * TT)          // 16384 rows
#define SCALE 0.03125f        // E^-0.5 = 1/32

// Scratch (device globals; no allocation allowed in kernel_launch)
__device__ float g_Q[BT * HH];
__device__ float g_K[BT * HH];
__device__ float g_V[BT * HH];
__device__ float g_M[BB * HH * HH];   // per-batch K^T V

// ---------------------------------------------------------------------------
// Kernel 1: QKV projection.  out[m][n] = sum_k X[m][k] * W[k][n] + bias[n]
// M=16384, N=64, K=1024. BM=128, BN=64, BK=16, 256 threads, 8x4 per thread.
// which: 0 -> g_Q, 1 -> g_K, 2 -> g_V
// ---------------------------------------------------------------------------
__global__ __launch_bounds__(256) void qkv_kernel(
    const float* __restrict__ X,
    const float* __restrict__ W,
    const float* __restrict__ bias,
    int which)
{
    __shared__ float Xs[16][132];   // [k][m], padded (132*4B = 33*16B, float4-aligned rows)
    __shared__ float Ws[16][64];    // [k][n]

    const int t  = threadIdx.x;
    const int tx = t & 15;          // n-tile: cols tx*4 .. tx*4+3
    const int ty = t >> 4;          // m-tile: rows ty*8 .. ty*8+7
    const int m0 = blockIdx.x * 128;

    float* __restrict__ outp = (which == 0) ? g_Q : (which == 1) ? g_K : g_V;

    float acc[8][4];
#pragma unroll
    for (int i = 0; i < 8; i++)
#pragma unroll
        for (int j = 0; j < 4; j++) acc[i][j] = 0.f;

    const float4* X4 = (const float4*)(X + (size_t)m0 * EE);
    const float4* W4 = (const float4*)W;

    for (int k0 = 0; k0 < EE; k0 += 16) {
        // Load X tile: 128 rows x 16 cols = 512 float4, 2 per thread (transposed store)
#pragma unroll
        for (int l = 0; l < 2; l++) {
            int f   = t + l * 256;
            int row = f >> 2;
            int c4  = f & 3;
            float4 v = X4[row * (EE / 4) + (k0 >> 2) + c4];
            Xs[c4 * 4 + 0][row] = v.x;
            Xs[c4 * 4 + 1][row] = v.y;
            Xs[c4 * 4 + 2][row] = v.z;
            Xs[c4 * 4 + 3][row] = v.w;
        }
        // Load W tile: 16 rows x 64 cols = 256 float4, 1 per thread
        {
            int row = t >> 4;
            int c4  = t & 15;
            float4 wv = W4[(k0 + row) * 16 + c4];
            *(float4*)&Ws[row][c4 * 4] = wv;
        }
        __syncthreads();

#pragma unroll
        for (int k = 0; k < 16; k++) {
            float4 b4 = *(const float4*)&Ws[k][tx * 4];
            float4 a0 = *(const float4*)&Xs[k][ty * 8];
            float4 a1 = *(const float4*)&Xs[k][ty * 8 + 4];
            float a[8] = {a0.x, a0.y, a0.z, a0.w, a1.x, a1.y, a1.z, a1.w};
            float bb[4] = {b4.x, b4.y, b4.z, b4.w};
#pragma unroll
            for (int i = 0; i < 8; i++)
#pragma unroll
                for (int j = 0; j < 4; j++)
                    acc[i][j] += a[i] * bb[j];
        }
        __syncthreads();
    }

    // Epilogue: bias + store
    float bl0 = bias[tx * 4 + 0];
    float bl1 = bias[tx * 4 + 1];
    float bl2 = bias[tx * 4 + 2];
    float bl3 = bias[tx * 4 + 3];
#pragma unroll
    for (int i = 0; i < 8; i++) {
        int r = m0 + ty * 8 + i;
        float4 o;
        o.x = acc[i][0] + bl0;
        o.y = acc[i][1] + bl1;
        o.z = acc[i][2] + bl2;
        o.w = acc[i][3] + bl3;
        *(float4*)&outp[(size_t)r * HH + tx * 4] = o;
    }
}

// ---------------------------------------------------------------------------
// Kernel 2: zero g_M
// ---------------------------------------------------------------------------
__global__ void zero_m_kernel()
{
    int i = blockIdx.x * blockDim.x + threadIdx.x;
    if (i < BB * HH * HH) g_M[i] = 0.f;
}

// ---------------------------------------------------------------------------
// Kernel 3: M[b] += K[b]^T @ V[b] over a chunk of CS rows; atomicAdd combine.
// grid = (T/CS, B), 256 threads, each thread owns a 4x4 tile of the 64x64 M.
// ---------------------------------------------------------------------------
#define CS 256
__global__ __launch_bounds__(256) void kv_outer_kernel()
{
    __shared__ float Ks[32][68];
    __shared__ float Vs[32][68];

    const int t  = threadIdx.x;
    const int tx = t & 15;   // h2: cols tx*4..+3
    const int ty = t >> 4;   // h1: rows ty*4..+3
    const int b  = blockIdx.y;
    const int s0 = blockIdx.x * CS;

    const float4* K4 = (const float4*)(g_K + ((size_t)b * TT + s0) * HH);
    const float4* V4 = (const float4*)(g_V + ((size_t)b * TT + s0) * HH);

    float acc[4][4];
#pragma unroll
    for (int i = 0; i < 4; i++)
#pragma unroll
        for (int j = 0; j < 4; j++) acc[i][j] = 0.f;

    for (int ss = 0; ss < CS; ss += 32) {
        // 32 rows x 64 cols = 512 float4 per tensor, 2 per thread each
#pragma unroll
        for (int l = 0; l < 2; l++) {
            int f   = t + l * 256;
            int row = f >> 4;
            int c4  = f & 15;
            float4 kv = K4[((size_t)(ss + row)) * 16 + c4];
            float4 vv = V4[((size_t)(ss + row)) * 16 + c4];
            *(float4*)&Ks[row][c4 * 4] = kv;
            *(float4*)&Vs[row][c4 * 4] = vv;
        }
        __syncthreads();

#pragma unroll 8
        for (int s = 0; s < 32; s++) {
            float4 a4 = *(const float4*)&Ks[s][ty * 4];
            float4 b4 = *(const float4*)&Vs[s][tx * 4];
            float a[4] = {a4.x, a4.y, a4.z, a4.w};
            float bb[4] = {b4.x, b4.y, b4.z, b4.w};
#pragma unroll
            for (int i = 0; i < 4; i++)
#pragma unroll
                for (int j = 0; j < 4; j++)
                    acc[i][j] += a[i] * bb[j];
        }
        __syncthreads();
    }

    float* Mb = g_M + (size_t)b * HH * HH;
#pragma unroll
    for (int i = 0; i < 4; i++)
#pragma unroll
        for (int j = 0; j < 4; j++)
            atomicAdd(&Mb[(ty * 4 + i) * HH + tx * 4 + j], acc[i][j]);
}

// ---------------------------------------------------------------------------
// Kernel 4: out[b] = SCALE * Q[b] @ M[b].  grid = BT/64 blocks of 64 rows.
// ---------------------------------------------------------------------------
__global__ __launch_bounds__(256) void out_kernel(float* __restrict__ out)
{
    __shared__ float Ms[64][68];
    __shared__ float Qs[64][68];

    const int t    = threadIdx.x;
    const int tx   = t & 15;   // cols tx*4..+3
    const int ty   = t >> 4;   // rows ty*4..+3 (local)
    const int row0 = blockIdx.x * 64;
    const int b    = row0 / TT;   // 64-row tiles never straddle batches (4096 % 64 == 0)

    const float4* Q4 = (const float4*)(g_Q + (size_t)row0 * HH);
    const float4* M4 = (const float4*)(g_M + (size_t)b * HH * HH);

    // Load Q tile and M (each 64x64 = 1024 float4, 4 per thread)
#pragma unroll
    for (int l = 0; l < 4; l++) {
        int f   = t + l * 256;
        int row = f >> 4;
        int c4  = f & 15;
        float4 qv = Q4[(size_t)row * 16 + c4];
        float4 mv = M4[(size_t)row * 16 + c4];
        *(float4*)&Qs[row][c4 * 4] = qv;
        *(float4*)&Ms[row][c4 * 4] = mv;
    }
    __syncthreads();

    float acc[4][4];
#pragma unroll
    for (int i = 0; i < 4; i++)
#pragma unroll
        for (int j = 0; j < 4; j++) acc[i][j] = 0.f;

#pragma unroll 4
    for (int k0 = 0; k0 < 64; k0 += 4) {
        float4 q4[4];
#pragma unroll
        for (int i = 0; i < 4; i++)
            q4[i] = *(const float4*)&Qs[ty * 4 + i][k0];
#pragma unroll
        for (int kk = 0; kk < 4; kk++) {
            float4 m4 = *(const float4*)&Ms[k0 + kk][tx * 4];
            float m[4] = {m4.x, m4.y, m4.z, m4.w};
#pragma unroll
            for (int i = 0; i < 4; i++) {
                float qv = (kk == 0) ? q4[i].x : (kk == 1) ? q4[i].y
                         : (kk == 2) ? q4[i].z : q4[i].w;
#pragma unroll
                for (int j = 0; j < 4; j++)
                    acc[i][j] += qv * m[j];
            }
        }
    }

#pragma unroll
    for (int i = 0; i < 4; i++) {
        int r = row0 + ty * 4 + i;
        float4 o;
        o.x = acc[i][0] * SCALE;
        o.y = acc[i][1] * SCALE;
        o.z = acc[i][2] * SCALE;
        o.w = acc[i][3] * SCALE;
        *(float4*)&out[(size_t)r * HH + tx * 4] = o;
    }
}

// ---------------------------------------------------------------------------
// Launch
// ---------------------------------------------------------------------------
extern "C" void kernel_launch(void* const* d_in, const int* in_sizes, int n_in,
                              void* d_out, int out_size)
{
    const float* idx = (const float*)d_in[0];
    const float* Wq  = (const float*)d_in[1];
    const float* bq  = (const float*)d_in[2];
    const float* Wk  = (const float*)d_in[3];
    const float* bk  = (const float*)d_in[4];
    const float* Wv  = (const float*)d_in[5];
    const float* bv  = (const float*)d_in[6];
    float* out = (float*)d_out;

    zero_m_kernel<<<(BB * HH * HH + 255) / 256, 256>>>();

    qkv_kernel<<<BT / 128, 256>>>(idx, Wq, bq, 0);
    qkv_kernel<<<BT / 128, 256>>>(idx, Wk, bk, 1);
    qkv_kernel<<<BT / 128, 256>>>(idx, Wv, bv, 2);

    kv_outer_kernel<<<dim3(TT / CS, BB), 256>>>();

    out_kernel<<<BT / 64, 256>>>(out);
}

// round 3
// speedup vs baseline: 2.1619x; 2.1619x over previous
#include <cuda_runtime.h>
#include <cuda_bf16.h>
#include <cstdint>

// Problem dims (fixed)
#define BB 4
#define TT 4096
#define EE 1024
#define HH 64
#define BT (BB * TT)          // 16384 rows
#define SCALE 0.03125f        // E^-0.5 = 1/32

// Scratch (device globals; no allocation allowed)
__device__ float g_Q[BT * HH];
__device__ float g_K[BT * HH];
__device__ float g_V[BT * HH];
__device__ float g_M[BB * HH * HH];             // per-batch K^T V
__device__ __nv_bfloat16 g_WT_hi[192 * EE];     // [n][k], n = {q:0-63,k:64-127,v:128-191}
__device__ __nv_bfloat16 g_WT_lo[192 * EE];

// ---------------------------------------------------------------------------
// Prep: split-convert Wq|Wk|Wv (fp32 [k][n]) -> bf16 hi/lo transposed [n][k]
// ---------------------------------------------------------------------------
__global__ void prep_w_kernel(const float* __restrict__ Wq,
                              const float* __restrict__ Wk,
                              const float* __restrict__ Wv)
{
    int i = blockIdx.x * blockDim.x + threadIdx.x;   // 0 .. 192*1024-1
    if (i >= 192 * EE) return;
    int n = i % 192;
    int k = i / 192;
    int which = n >> 6;
    int nc = n & 63;
    const float* W = (which == 0) ? Wq : (which == 1) ? Wk : Wv;
    float v = W[k * HH + nc];
    __nv_bfloat16 hi = __float2bfloat16_rn(v);
    __nv_bfloat16 lo = __float2bfloat16_rn(v - __bfloat162float(hi));
    g_WT_hi[(size_t)n * EE + k] = hi;
    g_WT_lo[(size_t)n * EE + k] = lo;
}

// ---------------------------------------------------------------------------
// QKV projection via bf16x3 split mma.sync.m16n8k16.
// grid = (BT/128, 3). Block 256 thr = 8 warps (4 over M x 2 over N).
// Warp tile: 32(M) x 32(N). BK = 32 (2 k16 steps).
// ---------------------------------------------------------------------------
#define MMA_BF16(c, a, b)                                                     \
    asm volatile(                                                             \
        "mma.sync.aligned.m16n8k16.row.col.f32.bf16.bf16.f32 "                \
        "{%0,%1,%2,%3}, {%4,%5,%6,%7}, {%8,%9}, {%0,%1,%2,%3};\n"             \
        : "+f"(c[0]), "+f"(c[1]), "+f"(c[2]), "+f"(c[3])                      \
        : "r"(a[0]), "r"(a[1]), "r"(a[2]), "r"(a[3]), "r"(b[0]), "r"(b[1]))

__global__ __launch_bounds__(256) void qkv_mma_kernel(
    const float* __restrict__ X,
    const float* __restrict__ bq,
    const float* __restrict__ bkk,
    const float* __restrict__ bv)
{
    __shared__ __nv_bfloat16 Xh[128][40];
    __shared__ __nv_bfloat16 Xl[128][40];
    __shared__ __nv_bfloat16 Wh[64][40];
    __shared__ __nv_bfloat16 Wl[64][40];

    const int t    = threadIdx.x;
    const int warp = t >> 5;
    const int lane = t & 31;
    const int g    = lane >> 2;      // group id 0..7
    const int tig  = lane & 3;       // thread-in-group 0..3
    const int wm   = warp >> 1;      // 0..3 -> m offset 32*wm
    const int wn   = warp & 1;       // 0..1 -> n offset 32*wn
    const int m0   = blockIdx.x * 128;
    const int which = blockIdx.y;

    const __nv_bfloat16* WTh = g_WT_hi + (size_t)which * 64 * EE;
    const __nv_bfloat16* WTl = g_WT_lo + (size_t)which * 64 * EE;
    const float4* X4 = (const float4*)X;

    float c[2][4][4];
#pragma unroll
    for (int mt = 0; mt < 2; mt++)
#pragma unroll
        for (int nt = 0; nt < 4; nt++)
#pragma unroll
            for (int j = 0; j < 4; j++) c[mt][nt][j] = 0.f;

    for (int k0 = 0; k0 < EE; k0 += 32) {
        // --- X tile: 128 rows x 32 cols fp32 -> split bf16 hi/lo ---
#pragma unroll
        for (int l = 0; l < 4; l++) {
            int f   = t + l * 256;       // 0..1023
            int row = f >> 3;            // 0..127
            int c4  = f & 7;             // 0..7 (float4 chunk)
            float4 v = X4[(size_t)(m0 + row) * (EE / 4) + (k0 >> 2) + c4];
            float vv[4] = {v.x, v.y, v.z, v.w};
            __nv_bfloat16 hb[4], lb[4];
#pragma unroll
            for (int j = 0; j < 4; j++) {
                hb[j] = __float2bfloat16_rn(vv[j]);
                lb[j] = __float2bfloat16_rn(vv[j] - __bfloat162float(hb[j]));
            }
            uint2 hp, lp;
            hp.x = ((uint32_t)__bfloat16_as_ushort(hb[1]) << 16) | __bfloat16_as_ushort(hb[0]);
            hp.y = ((uint32_t)__bfloat16_as_ushort(hb[3]) << 16) | __bfloat16_as_ushort(hb[2]);
            lp.x = ((uint32_t)__bfloat16_as_ushort(lb[1]) << 16) | __bfloat16_as_ushort(lb[0]);
            lp.y = ((uint32_t)__bfloat16_as_ushort(lb[3]) << 16) | __bfloat16_as_ushort(lb[2]);
            *(uint2*)&Xh[row][c4 * 4] = hp;
            *(uint2*)&Xl[row][c4 * 4] = lp;
        }
        // --- W tiles: 64 rows(n) x 32 cols(k) bf16, hi and lo planes ---
        {
            int row = t >> 2;            // 0..63
            int ch  = t & 3;             // 0..3 (8 halves = 16B each)
            *(uint4*)&Wh[row][ch * 8] =
                *(const uint4*)(WTh + (size_t)row * EE + k0 + ch * 8);
            *(uint4*)&Wl[row][ch * 8] =
                *(const uint4*)(WTl + (size_t)row * EE + k0 + ch * 8);
        }
        __syncthreads();

#pragma unroll
        for (int ks = 0; ks < 2; ks++) {
            const int kb = ks * 16;
            uint32_t ah[2][4], al[2][4];
#pragma unroll
            for (int mt = 0; mt < 2; mt++) {
                int r = wm * 32 + mt * 16 + g;
                ah[mt][0] = *(const uint32_t*)&Xh[r][kb + 2 * tig];
                ah[mt][1] = *(const uint32_t*)&Xh[r + 8][kb + 2 * tig];
                ah[mt][2] = *(const uint32_t*)&Xh[r][kb + 2 * tig + 8];
                ah[mt][3] = *(const uint32_t*)&Xh[r + 8][kb + 2 * tig + 8];
                al[mt][0] = *(const uint32_t*)&Xl[r][kb + 2 * tig];
                al[mt][1] = *(const uint32_t*)&Xl[r + 8][kb + 2 * tig];
                al[mt][2] = *(const uint32_t*)&Xl[r][kb + 2 * tig + 8];
                al[mt][3] = *(const uint32_t*)&Xl[r + 8][kb + 2 * tig + 8];
            }
            uint32_t bh[4][2], bl[4][2];
#pragma unroll
            for (int nt = 0; nt < 4; nt++) {
                int n = wn * 32 + nt * 8 + g;
                bh[nt][0] = *(const uint32_t*)&Wh[n][kb + 2 * tig];
                bh[nt][1] = *(const uint32_t*)&Wh[n][kb + 2 * tig + 8];
                bl[nt][0] = *(const uint32_t*)&Wl[n][kb + 2 * tig];
                bl[nt][1] = *(const uint32_t*)&Wl[n][kb + 2 * tig + 8];
            }
#pragma unroll
            for (int mt = 0; mt < 2; mt++)
#pragma unroll
                for (int nt = 0; nt < 4; nt++) {
                    MMA_BF16(c[mt][nt], ah[mt], bh[nt]);   // hi*hi
                    MMA_BF16(c[mt][nt], ah[mt], bl[nt]);   // hi*lo
                    MMA_BF16(c[mt][nt], al[mt], bh[nt]);   // lo*hi
                }
        }
        __syncthreads();
    }

    // --- Epilogue: bias + store fp32 ---
    const float* bias = (which == 0) ? bq : (which == 1) ? bkk : bv;
    float* __restrict__ outp = (which == 0) ? g_Q : (which == 1) ? g_K : g_V;
#pragma unroll
    for (int mt = 0; mt < 2; mt++) {
        int r0 = m0 + wm * 32 + mt * 16 + g;
#pragma unroll
        for (int nt = 0; nt < 4; nt++) {
            int n = wn * 32 + nt * 8 + 2 * tig;
            float b0v = bias[n];
            float b1v = bias[n + 1];
            float2 o0 = {c[mt][nt][0] + b0v, c[mt][nt][1] + b1v};
            float2 o1 = {c[mt][nt][2] + b0v, c[mt][nt][3] + b1v};
            *(float2*)&outp[(size_t)r0 * HH + n] = o0;
            *(float2*)&outp[(size_t)(r0 + 8) * HH + n] = o1;
        }
    }
}

// ---------------------------------------------------------------------------
// Zero g_M
// ---------------------------------------------------------------------------
__global__ void zero_m_kernel()
{
    int i = blockIdx.x * blockDim.x + threadIdx.x;
    if (i < BB * HH * HH) g_M[i] = 0.f;
}

// ---------------------------------------------------------------------------
// M[b] += K[b]^T @ V[b] over CS-row chunks; atomicAdd combine. (fp32, tiny)
// ---------------------------------------------------------------------------
#define CS 256
__global__ __launch_bounds__(256) void kv_outer_kernel()
{
    __shared__ float Ks[32][68];
    __shared__ float Vs[32][68];

    const int t  = threadIdx.x;
    const int tx = t & 15;
    const int ty = t >> 4;
    const int b  = blockIdx.y;
    const int s0 = blockIdx.x * CS;

    const float4* K4 = (const float4*)(g_K + ((size_t)b * TT + s0) * HH);
    const float4* V4 = (const float4*)(g_V + ((size_t)b * TT + s0) * HH);

    float acc[4][4];
#pragma unroll
    for (int i = 0; i < 4; i++)
#pragma unroll
        for (int j = 0; j < 4; j++) acc[i][j] = 0.f;

    for (int ss = 0; ss < CS; ss += 32) {
#pragma unroll
        for (int l = 0; l < 2; l++) {
            int f   = t + l * 256;
            int row = f >> 4;
            int c4  = f & 15;
            float4 kv = K4[((size_t)(ss + row)) * 16 + c4];
            float4 vv = V4[((size_t)(ss + row)) * 16 + c4];
            *(float4*)&Ks[row][c4 * 4] = kv;
            *(float4*)&Vs[row][c4 * 4] = vv;
        }
        __syncthreads();

#pragma unroll 8
        for (int s = 0; s < 32; s++) {
            float4 a4 = *(const float4*)&Ks[s][ty * 4];
            float4 b4 = *(const float4*)&Vs[s][tx * 4];
            float a[4] = {a4.x, a4.y, a4.z, a4.w};
            float bb2[4] = {b4.x, b4.y, b4.z, b4.w};
#pragma unroll
            for (int i = 0; i < 4; i++)
#pragma unroll
                for (int j = 0; j < 4; j++)
                    acc[i][j] += a[i] * bb2[j];
        }
        __syncthreads();
    }

    float* Mb = g_M + (size_t)b * HH * HH;
#pragma unroll
    for (int i = 0; i < 4; i++)
#pragma unroll
        for (int j = 0; j < 4; j++)
            atomicAdd(&Mb[(ty * 4 + i) * HH + tx * 4 + j], acc[i][j]);
}

// ---------------------------------------------------------------------------
// out[b] = SCALE * Q[b] @ M[b]
// ---------------------------------------------------------------------------
__global__ __launch_bounds__(256) void out_kernel(float* __restrict__ out)
{
    __shared__ float Ms[64][68];
    __shared__ float Qs[64][68];

    const int t    = threadIdx.x;
    const int tx   = t & 15;
    const int ty   = t >> 4;
    const int row0 = blockIdx.x * 64;
    const int b    = row0 / TT;

    const float4* Q4 = (const float4*)(g_Q + (size_t)row0 * HH);
    const float4* M4 = (const float4*)(g_M + (size_t)b * HH * HH);

#pragma unroll
    for (int l = 0; l < 4; l++) {
        int f   = t + l * 256;
        int row = f >> 4;
        int c4  = f & 15;
        float4 qv = Q4[(size_t)row * 16 + c4];
        float4 mv = M4[(size_t)row * 16 + c4];
        *(float4*)&Qs[row][c4 * 4] = qv;
        *(float4*)&Ms[row][c4 * 4] = mv;
    }
    __syncthreads();

    float acc[4][4];
#pragma unroll
    for (int i = 0; i < 4; i++)
#pragma unroll
        for (int j = 0; j < 4; j++) acc[i][j] = 0.f;

#pragma unroll 4
    for (int k0 = 0; k0 < 64; k0 += 4) {
        float4 q4[4];
#pragma unroll
        for (int i = 0; i < 4; i++)
            q4[i] = *(const float4*)&Qs[ty * 4 + i][k0];
#pragma unroll
        for (int kk = 0; kk < 4; kk++) {
            float4 m4 = *(const float4*)&Ms[k0 + kk][tx * 4];
            float m[4] = {m4.x, m4.y, m4.z, m4.w};
#pragma unroll
            for (int i = 0; i < 4; i++) {
                float qv = (kk == 0) ? q4[i].x : (kk == 1) ? q4[i].y
                         : (kk == 2) ? q4[i].z : q4[i].w;
#pragma unroll
                for (int j = 0; j < 4; j++)
                    acc[i][j] += qv * m[j];
            }
        }
    }

#pragma unroll
    for (int i = 0; i < 4; i++) {
        int r = row0 + ty * 4 + i;
        float4 o;
        o.x = acc[i][0] * SCALE;
        o.y = acc[i][1] * SCALE;
        o.z = acc[i][2] * SCALE;
        o.w = acc[i][3] * SCALE;
        *(float4*)&out[(size_t)r * HH + tx * 4] = o;
    }
}

// ---------------------------------------------------------------------------
// Launch
// ---------------------------------------------------------------------------
extern "C" void kernel_launch(void* const* d_in, const int* in_sizes, int n_in,
                              void* d_out, int out_size)
{
    const float* idx = (const float*)d_in[0];
    const float* Wq  = (const float*)d_in[1];
    const float* bq  = (const float*)d_in[2];
    const float* Wk  = (const float*)d_in[3];
    const float* bk  = (const float*)d_in[4];
    const float* Wv  = (const float*)d_in[5];
    const float* bv  = (const float*)d_in[6];
    float* out = (float*)d_out;

    prep_w_kernel<<<(192 * EE + 255) / 256, 256>>>(Wq, Wk, Wv);
    zero_m_kernel<<<(BB * HH * HH + 255) / 256, 256>>>();

    qkv_mma_kernel<<<dim3(BT / 128, 3), 256>>>(idx, bq, bk, bv);

    kv_outer_kernel<<<dim3(TT / CS, BB), 256>>>();

    out_kernel<<<BT / 64, 256>>>(out);
}